// round 14
// baseline (speedup 1.0000x reference)
#include <cuda_runtime.h>
#include <cstdint>

// MemoryReader attention — software-pipelined: logit(t+1) + readout(t) in one
// unbarriered region, Et double-buffered, Q frags in registers, mbarrier-tracked
// cp.async V. 2 CTAs/SM (channel halves). XOR-swizzled unpadded smem tiles.
// R14 fix: cp.async.mbarrier.arrive needs .noinc (default variant increments
// pending count -> barrier never flips -> R13 deadlock).
//   B=16, CK=64, CV=512, N=3136, 64 queries/CTA, 64-key tiles.

#define Bsz     16
#define CKc     64
#define CVc     512
#define NPIX    3136
#define MQ      64
#define NT      64
#define THREADS 256
#define NTILES  49
#define CVH     256

// word offsets (unpadded 64-col tiles, XOR swizzled)
#define KH_OFF  0            // [32cp][64] bf16x2 hi, swz col^8(row&3)
#define KL_OFF  2048
#define EA_OFF  4096         // Et buf A [64q][64] tf32, swz col^4(row&7)
#define EB_OFF  8192         // Et buf B
#define VS_OFF  12288        // [256ch][64] fp32, swz col^4(row&7)
#define S2_OFF  28672
#define DN_OFF  28736
#define MB_OFF  28800        // mbarrier (8B)
#define SMEM_W  28816        // 115264 B/CTA

__device__ __forceinline__ float tf32r(float x) {
    uint32_t u; asm("cvt.rna.tf32.f32 %0, %1;" : "=r"(u) : "f"(x));
    return __uint_as_float(u);
}
__device__ __forceinline__ uint32_t bf16x2p(float odd, float even) {
    uint32_t r;
    asm("cvt.rn.bf16x2.f32 %0, %1, %2;" : "=r"(r) : "f"(odd), "f"(even));
    return r;
}
__device__ __forceinline__ float bfLO(uint32_t w) { return __uint_as_float(w << 16); }
__device__ __forceinline__ float bfHI(uint32_t w) { return __uint_as_float(w & 0xffff0000u); }

__device__ __forceinline__ void mma_tf32(float d[4], const uint32_t a[4], const uint32_t b[2]) {
    asm volatile(
        "mma.sync.aligned.m16n8k8.row.col.f32.tf32.tf32.f32 "
        "{%0,%1,%2,%3}, {%4,%5,%6,%7}, {%8,%9}, {%0,%1,%2,%3};"
        : "+f"(d[0]), "+f"(d[1]), "+f"(d[2]), "+f"(d[3])
        : "r"(a[0]), "r"(a[1]), "r"(a[2]), "r"(a[3]), "r"(b[0]), "r"(b[1]));
}
__device__ __forceinline__ void mma_bf16(float d[4], const uint32_t a[4], const uint32_t b[2]) {
    asm volatile(
        "mma.sync.aligned.m16n8k16.row.col.f32.bf16.bf16.f32 "
        "{%0,%1,%2,%3}, {%4,%5,%6,%7}, {%8,%9}, {%0,%1,%2,%3};"
        : "+f"(d[0]), "+f"(d[1]), "+f"(d[2]), "+f"(d[3])
        : "r"(a[0]), "r"(a[1]), "r"(a[2]), "r"(a[3]), "r"(b[0]), "r"(b[1]));
}
__device__ __forceinline__ void mbar_wait(uint32_t mbar, uint32_t par) {
    uint32_t done;
    asm volatile("{\n\t.reg .pred p;\n\t"
        "mbarrier.try_wait.parity.shared.b64 p, [%1], %2;\n\t"
        "selp.b32 %0, 1, 0, p;\n\t}" : "=r"(done) : "r"(mbar), "r"(par) : "memory");
    if (!done) {
        asm volatile("{\n\t.reg .pred P1;\n\tWL%=:\n\t"
            "mbarrier.try_wait.parity.shared.b64 P1, [%0], %1;\n\t"
            "@P1 bra.uni WD%=;\n\tbra.uni WL%=;\n\tWD%=:\n\t}"
            :: "r"(mbar), "r"(par) : "memory");
    }
}

__global__ __launch_bounds__(THREADS, 2)
void mr_attn_kernel(const float* __restrict__ mk, const float* __restrict__ qk,
                    const float* __restrict__ mv, float* __restrict__ out)
{
    extern __shared__ float sm[];
    float* S2 = sm + S2_OFF;
    float* Dn = sm + DN_OFF;
    uint32_t* KhW = (uint32_t*)(sm + KH_OFF);
    uint32_t* KlW = (uint32_t*)(sm + KL_OFF);
    float*    VsF = sm + VS_OFF;
    uint32_t* VsW = (uint32_t*)VsF;

    uint32_t sbase;
    asm("{ .reg .u64 t; cvta.to.shared.u64 t, %1; cvt.u32.u64 %0, t; }"
        : "=r"(sbase) : "l"(sm));
    const uint32_t mbar = sbase + MB_OFF * 4u;

    const int b    = blockIdx.y;
    const int m0   = blockIdx.x * MQ;
    const int zc   = blockIdx.z * CVH;
    const int tid  = threadIdx.x;
    const int wid  = tid >> 5;
    const int lane = tid & 31;
    const int g    = lane >> 2;
    const int tq   = lane & 3;

    const float* qb = qk + (size_t)b * CKc * NPIX + m0;
    const float* kb = mk + (size_t)b * CKc * NPIX;
    const float* vb = mv + ((size_t)b * CVc + zc) * NPIX;

    const int ch0 = wid * 32;
    const int wq  = wid & 3;
    const int wk  = wid >> 2;
    const int q0  = wq * 16;
    const int kh0 = wk * 32;

    // ---------- prologue ----------
    if (tid == 0) {
        asm volatile("mbarrier.init.shared.b64 [%0], %1;"
                     :: "r"(mbar), "r"((uint32_t)THREADS) : "memory");
    }
    // Stage Q hi/lo bf16x2 into V region (scratch), K layout/swizzle
    #pragma unroll
    for (int it = 0; it < 2; ++it) {
        int slot = it * THREADS + tid;
        int cp = slot >> 4, m4 = slot & 15;
        const float* q0p = qb + (2 * cp) * NPIX + 4 * m4;
        float4 qe = *(const float4*)(q0p);
        float4 qo = *(const float4*)(q0p + NPIX);
        float xe[4] = {qe.x, qe.y, qe.z, qe.w};
        float xo[4] = {qo.x, qo.y, qo.z, qo.w};
        uint32_t hv[4], lv[4];
        #pragma unroll
        for (int r = 0; r < 4; ++r) {
            uint32_t h = bf16x2p(xo[r], xe[r]);
            hv[r] = h;
            lv[r] = bf16x2p(xo[r] - bfHI(h), xe[r] - bfLO(h));
        }
        int sw = (4 * m4) ^ (8 * (cp & 3));
        *(uint4*)(VsW + cp * 64 + sw)        = *(uint4*)hv;
        *(uint4*)(VsW + 2048 + cp * 64 + sw) = *(uint4*)lv;
    }
    if (tid < MQ) Dn[tid] = 0.f;
    __syncthreads();

    // Q fragments -> registers (loop-invariant)
    uint32_t qh_r[4][4], ql_r[4][4];
    #pragma unroll
    for (int cs = 0; cs < 4; ++cs) {
        const int cb = cs * 8;
        qh_r[cs][0] = VsW[(cb + tq) * 64 + ((q0 + g) ^ (8 * tq))];
        qh_r[cs][1] = VsW[(cb + tq) * 64 + ((q0 + g + 8) ^ (8 * tq))];
        qh_r[cs][2] = VsW[(cb + tq + 4) * 64 + ((q0 + g) ^ (8 * (tq + 4) & 31)) ];
        // NOTE: swizzle for rows cb+tq+4 uses (cp&3) = tq (since cp=cb+tq+4, cb%4==0
        // -> (cp&3)==(tq+4)&3==tq... careful below
        qh_r[cs][2] = VsW[(cb + tq + 4) * 64 + ((q0 + g) ^ (8 * ((cb + tq + 4) & 3)))];
        qh_r[cs][3] = VsW[(cb + tq + 4) * 64 + ((q0 + g + 8) ^ (8 * ((cb + tq + 4) & 3)))];
        qh_r[cs][0] = VsW[(cb + tq) * 64 + ((q0 + g) ^ (8 * ((cb + tq) & 3)))];
        qh_r[cs][1] = VsW[(cb + tq) * 64 + ((q0 + g + 8) ^ (8 * ((cb + tq) & 3)))];
        ql_r[cs][0] = VsW[2048 + (cb + tq) * 64 + ((q0 + g) ^ (8 * ((cb + tq) & 3)))];
        ql_r[cs][1] = VsW[2048 + (cb + tq) * 64 + ((q0 + g + 8) ^ (8 * ((cb + tq) & 3)))];
        ql_r[cs][2] = VsW[2048 + (cb + tq + 4) * 64 + ((q0 + g) ^ (8 * ((cb + tq + 4) & 3)))];
        ql_r[cs][3] = VsW[2048 + (cb + tq + 4) * 64 + ((q0 + g + 8) ^ (8 * ((cb + tq + 4) & 3)))];
    }
    // K(0) convert (disjoint region, same phase)
    #pragma unroll
    for (int it = 0; it < 2; ++it) {
        int slot = it * THREADS + tid;
        int cp = slot >> 4, n4 = slot & 15;
        const float* k0p = kb + (2 * cp) * NPIX + 4 * n4;
        float4 ke = *(const float4*)(k0p);
        float4 ko = *(const float4*)(k0p + NPIX);
        float xe[4] = {ke.x, ke.y, ke.z, ke.w};
        float xo[4] = {ko.x, ko.y, ko.z, ko.w};
        uint32_t hv[4], lv[4];
        #pragma unroll
        for (int r = 0; r < 4; ++r) {
            uint32_t h = bf16x2p(xo[r], xe[r]);
            hv[r] = h;
            lv[r] = bf16x2p(xo[r] - bfHI(h), xe[r] - bfLO(h));
        }
        int sw = (4 * n4) ^ (8 * (cp & 3));
        *(uint4*)(KhW + cp * 64 + sw) = *(uint4*)hv;
        *(uint4*)(KlW + cp * 64 + sw) = *(uint4*)lv;
    }
    __syncthreads();   // Q frags extracted (V region free), K(0) ready

    // V(0) cp.async + mbarrier arrive (.noinc!)
    #pragma unroll
    for (int i = 0; i < 16; ++i) {
        int idx = i * THREADS + tid;
        int c = idx >> 4, n4 = idx & 15;
        int sw = (4 * n4) ^ (4 * (c & 7));
        uint32_t dst = sbase + (uint32_t)(VS_OFF + c * 64 + sw) * 4u;
        asm volatile("cp.async.cg.shared.global [%0], [%1], 16;"
                     :: "r"(dst), "l"(vb + c * NPIX + 4 * n4));
    }
    asm volatile("cp.async.mbarrier.arrive.noinc.shared.b64 [%0];" :: "r"(mbar) : "memory");

    // S2(0) + logit(0)
    {
        if (tid < NT) {
            float s = 0.f;
            #pragma unroll
            for (int cp = 0; cp < 32; ++cp) {
                int sw = tid ^ (8 * (cp & 3));
                uint32_t wh = KhW[cp * 64 + sw], wl = KlW[cp * 64 + sw];
                float ke = bfLO(wh) + bfLO(wl);
                float ko = bfHI(wh) + bfHI(wl);
                s = fmaf(ke, ke, fmaf(ko, ko, s));
            }
            S2[tid] = s;
        }
        float dl[4][4];
        #pragma unroll
        for (int j = 0; j < 4; ++j)
            #pragma unroll
            for (int r = 0; r < 4; ++r) dl[j][r] = 0.f;
        #pragma unroll
        for (int cs = 0; cs < 4; ++cs) {
            const int cb = cs * 8;
            #pragma unroll
            for (int j = 0; j < 4; ++j) {
                const int kk0 = kh0 + 8 * j;
                uint32_t bh[2], bl2[2];
                bh[0]  = KhW[(cb + tq) * 64 + ((kk0 + g) ^ (8 * ((cb + tq) & 3)))];
                bh[1]  = KhW[(cb + tq + 4) * 64 + ((kk0 + g) ^ (8 * ((cb + tq + 4) & 3)))];
                bl2[0] = KlW[(cb + tq) * 64 + ((kk0 + g) ^ (8 * ((cb + tq) & 3)))];
                bl2[1] = KlW[(cb + tq + 4) * 64 + ((kk0 + g) ^ (8 * ((cb + tq + 4) & 3)))];
                mma_bf16(dl[j], qh_r[cs], bh);
                mma_bf16(dl[j], qh_r[cs], bl2);
                mma_bf16(dl[j], ql_r[cs], bh);
            }
        }
        __syncthreads();   // K(0) reads + S2 done

        // exp -> Et buf A (tile 0) + Dn
        float* Et0 = sm + EA_OFF;
        const float C1 = 0.125f * 1.4426950408889634f;
        float pA = 0.f, pB = 0.f;
        #pragma unroll
        for (int j = 0; j < 4; ++j) {
            const int kk = kh0 + 8 * j + 2 * tq;
            float2 s2v = *(const float2*)(S2 + kk);
            float sbx = s2v.x * C1, sby = s2v.y * C1;
            float e0 = exp2f(fmaf(dl[j][0], 2.f * C1, -sbx));
            float e1 = exp2f(fmaf(dl[j][1], 2.f * C1, -sby));
            float e2 = exp2f(fmaf(dl[j][2], 2.f * C1, -sbx));
            float e3 = exp2f(fmaf(dl[j][3], 2.f * C1, -sby));
            int sw = kk ^ (4 * ((q0 + g) & 7));
            int sw2 = kk ^ (4 * ((q0 + g + 8) & 7));
            *(float2*)(Et0 + (q0 + g) * 64 + sw)      = make_float2(tf32r(e0), tf32r(e1));
            *(float2*)(Et0 + (q0 + g + 8) * 64 + sw2) = make_float2(tf32r(e2), tf32r(e3));
            pA += e0 + e1;
            pB += e2 + e3;
        }
        pA += __shfl_xor_sync(0xffffffffu, pA, 1);
        pA += __shfl_xor_sync(0xffffffffu, pA, 2);
        pB += __shfl_xor_sync(0xffffffffu, pB, 1);
        pB += __shfl_xor_sync(0xffffffffu, pB, 2);
        if (tq == 0) {
            atomicAdd(&Dn[q0 + g], pA);
            atomicAdd(&Dn[q0 + g + 8], pB);
        }
    }

    // Readout accumulators
    float d[2][8][4];
    #pragma unroll
    for (int i = 0; i < 2; ++i)
        #pragma unroll
        for (int j = 0; j < 8; ++j)
            #pragma unroll
            for (int r = 0; r < 4; ++r) d[i][j][r] = 0.f;

    // ---------- main pipelined loop ----------
    #pragma unroll 1
    for (int t = 0; t < NTILES; ++t) {
        const bool prod = (t + 1 < NTILES);

        // A: K(t+1) convert
        if (prod) {
            const int n0 = (t + 1) * NT;
            #pragma unroll
            for (int it = 0; it < 2; ++it) {
                int slot = it * THREADS + tid;
                int cp = slot >> 4, n4 = slot & 15;
                const float* k0p = kb + (2 * cp) * NPIX + n0 + 4 * n4;
                float4 ke = *(const float4*)(k0p);
                float4 ko = *(const float4*)(k0p + NPIX);
                float xe[4] = {ke.x, ke.y, ke.z, ke.w};
                float xo[4] = {ko.x, ko.y, ko.z, ko.w};
                uint32_t hv[4], lv[4];
                #pragma unroll
                for (int r = 0; r < 4; ++r) {
                    uint32_t h = bf16x2p(xo[r], xe[r]);
                    hv[r] = h;
                    lv[r] = bf16x2p(xo[r] - bfHI(h), xe[r] - bfLO(h));
                }
                int sw = (4 * n4) ^ (8 * (cp & 3));
                *(uint4*)(KhW + cp * 64 + sw) = *(uint4*)hv;
                *(uint4*)(KlW + cp * 64 + sw) = *(uint4*)lv;
            }
        }
        __syncthreads();   // B1: K(t+1) ready; Et(t) ready

        // C: S2(t+1) + logit(t+1) -> dl (registers)
        float dl[4][4];
        if (prod) {
            if (tid < NT) {
                float s = 0.f;
                #pragma unroll
                for (int cp = 0; cp < 32; ++cp) {
                    int sw = tid ^ (8 * (cp & 3));
                    uint32_t wh = KhW[cp * 64 + sw], wl = KlW[cp * 64 + sw];
                    float ke = bfLO(wh) + bfLO(wl);
                    float ko = bfHI(wh) + bfHI(wl);
                    s = fmaf(ke, ke, fmaf(ko, ko, s));
                }
                S2[tid] = s;
            }
            #pragma unroll
            for (int j = 0; j < 4; ++j)
                #pragma unroll
                for (int r = 0; r < 4; ++r) dl[j][r] = 0.f;
            #pragma unroll
            for (int cs = 0; cs < 4; ++cs) {
                const int cb = cs * 8;
                #pragma unroll
                for (int j = 0; j < 4; ++j) {
                    const int kk0 = kh0 + 8 * j;
                    uint32_t bh[2], bl2[2];
                    bh[0]  = KhW[(cb + tq) * 64 + ((kk0 + g) ^ (8 * ((cb + tq) & 3)))];
                    bh[1]  = KhW[(cb + tq + 4) * 64 + ((kk0 + g) ^ (8 * ((cb + tq + 4) & 3)))];
                    bl2[0] = KlW[(cb + tq) * 64 + ((kk0 + g) ^ (8 * ((cb + tq) & 3)))];
                    bl2[1] = KlW[(cb + tq + 4) * 64 + ((kk0 + g) ^ (8 * ((cb + tq + 4) & 3)))];
                    mma_bf16(dl[j], qh_r[cs], bh);
                    mma_bf16(dl[j], qh_r[cs], bl2);
                    mma_bf16(dl[j], ql_r[cs], bh);
                }
            }
        }

        // wait V(t) (per-thread mbarrier; no CTA barrier -> drift preserved)
        mbar_wait(mbar, (uint32_t)(t & 1));

        // D: readout(t) from Et(t) and V(t)
        {
            const uint32_t* Eu = (const uint32_t*)(sm + ((t & 1) ? EB_OFF : EA_OFF));
            #pragma unroll
            for (int s = 0; s < 8; ++s) {
                const int k0 = s * 8;
                uint32_t a[2][4];
                #pragma unroll
                for (int i = 0; i < 2; ++i) {
                    int r0 = ch0 + 16 * i + g, r1 = r0 + 8;
                    a[i][0] = VsW[r0 * 64 + ((k0 + tq) ^ (4 * (r0 & 7)))];
                    a[i][1] = VsW[r1 * 64 + ((k0 + tq) ^ (4 * (r1 & 7)))];
                    a[i][2] = VsW[r0 * 64 + ((k0 + tq + 4) ^ (4 * (r0 & 7)))];
                    a[i][3] = VsW[r1 * 64 + ((k0 + tq + 4) ^ (4 * (r1 & 7)))];
                }
                uint32_t bfr[8][2];
                #pragma unroll
                for (int j = 0; j < 8; ++j) {
                    int q = j * 8 + g;
                    bfr[j][0] = Eu[q * 64 + ((k0 + tq) ^ (4 * (q & 7)))];
                    bfr[j][1] = Eu[q * 64 + ((k0 + tq + 4) ^ (4 * (q & 7)))];
                }
                #pragma unroll
                for (int i = 0; i < 2; ++i)
                    #pragma unroll
                    for (int j = 0; j < 8; ++j)
                        mma_tf32(d[i][j], a[i], bfr[j]);
            }
        }
        __syncthreads();   // B2: Et(t)/V(t) free

        // E: exp -> Et(t+1), Dn, cp.async V(t+1) + arrive (.noinc)
        if (prod) {
            float* EtN = sm + (((t + 1) & 1) ? EB_OFF : EA_OFF);
            const float C1 = 0.125f * 1.4426950408889634f;
            float pA = 0.f, pB = 0.f;
            #pragma unroll
            for (int j = 0; j < 4; ++j) {
                const int kk = kh0 + 8 * j + 2 * tq;
                float2 s2v = *(const float2*)(S2 + kk);
                float sbx = s2v.x * C1, sby = s2v.y * C1;
                float e0 = exp2f(fmaf(dl[j][0], 2.f * C1, -sbx));
                float e1 = exp2f(fmaf(dl[j][1], 2.f * C1, -sby));
                float e2 = exp2f(fmaf(dl[j][2], 2.f * C1, -sbx));
                float e3 = exp2f(fmaf(dl[j][3], 2.f * C1, -sby));
                int sw = kk ^ (4 * ((q0 + g) & 7));
                int sw2 = kk ^ (4 * ((q0 + g + 8) & 7));
                *(float2*)(EtN + (q0 + g) * 64 + sw)      = make_float2(tf32r(e0), tf32r(e1));
                *(float2*)(EtN + (q0 + g + 8) * 64 + sw2) = make_float2(tf32r(e2), tf32r(e3));
                pA += e0 + e1;
                pB += e2 + e3;
            }
            pA += __shfl_xor_sync(0xffffffffu, pA, 1);
            pA += __shfl_xor_sync(0xffffffffu, pA, 2);
            pB += __shfl_xor_sync(0xffffffffu, pB, 1);
            pB += __shfl_xor_sync(0xffffffffu, pB, 2);
            if (tq == 0) {
                atomicAdd(&Dn[q0 + g], pA);
                atomicAdd(&Dn[q0 + g + 8], pB);
            }
            const int n0n = (t + 1) * NT;
            #pragma unroll
            for (int i = 0; i < 16; ++i) {
                int idx = i * THREADS + tid;
                int c = idx >> 4, n4 = idx & 15;
                int sw = (4 * n4) ^ (4 * (c & 7));
                uint32_t dst = sbase + (uint32_t)(VS_OFF + c * 64 + sw) * 4u;
                asm volatile("cp.async.cg.shared.global [%0], [%1], 16;"
                             :: "r"(dst), "l"(vb + c * NPIX + n0n + 4 * n4));
            }
            asm volatile("cp.async.mbarrier.arrive.noinc.shared.b64 [%0];" :: "r"(mbar) : "memory");
        }
    }

    __syncthreads();
    if (tid < MQ) Dn[tid] = 1.0f / Dn[tid];
    __syncthreads();

    // Epilogue
    #pragma unroll
    for (int i = 0; i < 2; ++i) {
        int ch = zc + ch0 + 16 * i + g;
        float* op0 = out + ((size_t)b * CVc + ch) * NPIX + m0;
        float* op1 = out + ((size_t)b * CVc + ch + 8) * NPIX + m0;
        #pragma unroll
        for (int j = 0; j < 8; ++j) {
            int q = j * 8 + 2 * tq;
            float2 dn2 = *(const float2*)(Dn + q);
            *(float2*)(op0 + q) = make_float2(d[i][j][0] * dn2.x, d[i][j][1] * dn2.y);
            *(float2*)(op1 + q) = make_float2(d[i][j][2] * dn2.x, d[i][j][3] * dn2.y);
        }
    }
}

extern "C" void kernel_launch(void* const* d_in, const int* in_sizes, int n_in,
                              void* d_out, int out_size)
{
    const float* mk = (const float*)d_in[0];
    const float* qk = (const float*)d_in[1];
    const float* mv = (const float*)d_in[2];
    const float* qv = (const float*)d_in[3];
    float* out = (float*)d_out;

    size_t smem = (size_t)SMEM_W * sizeof(float);   // 115264 B
    cudaFuncSetAttribute(mr_attn_kernel, cudaFuncAttributeMaxDynamicSharedMemorySize, (int)smem);

    dim3 grid(NPIX / MQ, Bsz, 2);   // 49 x 16 x 2
    mr_attn_kernel<<<grid, THREADS, smem>>>(mk, qk, mv, out);

    size_t memElems = (size_t)Bsz * CVc * NPIX;
    if ((size_t)out_size >= 2 * memElems) {
        cudaMemcpyAsync(out + memElems, qv, memElems * sizeof(float),
                        cudaMemcpyDeviceToDevice);
    }
}

// round 15
// speedup vs baseline: 1.0569x; 1.0569x over previous
#include <cuda_runtime.h>
#include <cstdint>

// MemoryReader attention — tensor-pipe logits (bf16 3-split) + tf32 readout.
// R15 = R12 base (known 1666us) with: K pitch 72 (fixes 2-way logit frag
// conflict), Q frags in registers (kills logit A-frag LDS), K(t+1) prefetched
// raw fp32 via cp.async during readout(t) (removes exposed LDG latency).
// 2 CTAs/SM (channel halves). Plain wait_group/syncthreads sync only.
//   B=16, CK=64, CV=512, N=3136, 64 queries/CTA, 64-key tiles.

#define Bsz     16
#define CKc     64
#define CVc     512
#define NPIX    3136
#define MQ      64
#define NT      64
#define THREADS 256
#define NTILES  49
#define CVH     256

#define KP 72    // K hi/lo + Q-stage pitch: banks (8tq+g) bijective
#define P  68    // Et / V pitch: banks (4g+tq) bijective

// smem word offsets (per CTA: 26240 words = 104960 B)
#define KH_OFF 0                 // Kh [32cp][KP]  (Q staged here in prologue)
#define KL_OFF 2304              // Kl [32cp][KP]
#define ET_OFF 0                 // Et [64q][P] tf32 — OVERLAYS Kh/Kl (K dead post-logit)
#define VS_OFF 4608              // V  [256ch][P] raw fp32
#define KR_OFF 22016             // Kraw [64c][64k] fp32 (cp.async prefetch)
#define S2_OFF 26112
#define DN_OFF 26176
#define SMEM_W 26240

__device__ __forceinline__ float tf32r(float x) {
    uint32_t u; asm("cvt.rna.tf32.f32 %0, %1;" : "=r"(u) : "f"(x));
    return __uint_as_float(u);
}
__device__ __forceinline__ uint32_t bf16x2p(float odd, float even) {
    uint32_t r;
    asm("cvt.rn.bf16x2.f32 %0, %1, %2;" : "=r"(r) : "f"(odd), "f"(even));
    return r;
}
__device__ __forceinline__ float bfLO(uint32_t w) { return __uint_as_float(w << 16); }
__device__ __forceinline__ float bfHI(uint32_t w) { return __uint_as_float(w & 0xffff0000u); }

__device__ __forceinline__ void mma_tf32(float d[4], const uint32_t a[4], const uint32_t b[2]) {
    asm volatile(
        "mma.sync.aligned.m16n8k8.row.col.f32.tf32.tf32.f32 "
        "{%0,%1,%2,%3}, {%4,%5,%6,%7}, {%8,%9}, {%0,%1,%2,%3};"
        : "+f"(d[0]), "+f"(d[1]), "+f"(d[2]), "+f"(d[3])
        : "r"(a[0]), "r"(a[1]), "r"(a[2]), "r"(a[3]), "r"(b[0]), "r"(b[1]));
}
__device__ __forceinline__ void mma_bf16(float d[4], const uint32_t a[4], const uint32_t b[2]) {
    asm volatile(
        "mma.sync.aligned.m16n8k16.row.col.f32.bf16.bf16.f32 "
        "{%0,%1,%2,%3}, {%4,%5,%6,%7}, {%8,%9}, {%0,%1,%2,%3};"
        : "+f"(d[0]), "+f"(d[1]), "+f"(d[2]), "+f"(d[3])
        : "r"(a[0]), "r"(a[1]), "r"(a[2]), "r"(a[3]), "r"(b[0]), "r"(b[1]));
}
__device__ __forceinline__ void cpasync16(uint32_t dst, const void* src) {
    asm volatile("cp.async.cg.shared.global [%0], [%1], 16;" :: "r"(dst), "l"(src));
}

__global__ __launch_bounds__(THREADS, 2)
void mr_attn_kernel(const float* __restrict__ mk, const float* __restrict__ qk,
                    const float* __restrict__ mv, float* __restrict__ out)
{
    extern __shared__ float sm[];
    float* Et  = sm + ET_OFF;
    float* S2  = sm + S2_OFF;
    float* Dn  = sm + DN_OFF;
    float* KrF = sm + KR_OFF;
    uint32_t* KhW = (uint32_t*)(sm + KH_OFF);
    uint32_t* KlW = (uint32_t*)(sm + KL_OFF);
    uint32_t* VsW = (uint32_t*)(sm + VS_OFF);

    uint32_t sbase;
    asm("{ .reg .u64 t; cvta.to.shared.u64 t, %1; cvt.u32.u64 %0, t; }"
        : "=r"(sbase) : "l"(sm));

    const int b    = blockIdx.y;
    const int m0   = blockIdx.x * MQ;
    const int zc   = blockIdx.z * CVH;
    const int tid  = threadIdx.x;
    const int wid  = tid >> 5;
    const int lane = tid & 31;
    const int g    = lane >> 2;
    const int tq   = lane & 3;

    const float* qb = qk + (size_t)b * CKc * NPIX + m0;
    const float* kb = mk + (size_t)b * CKc * NPIX;
    const float* vb = mv + ((size_t)b * CVc + zc) * NPIX;

    const int ch0 = wid * 32;        // readout channel slab
    const int wq  = wid & 3;         // logit q m-tile (16q)
    const int wk  = wid >> 2;        // logit k half (32k)
    const int q0  = wq * 16;
    const int kh0 = wk * 32;

    // ---------- prologue ----------
    // Kraw(0) + V(0) in flight ASAP (groups: Kraw older, then V)
    #pragma unroll
    for (int i = 0; i < 4; ++i) {
        int idx = i * THREADS + tid;
        int c = idx >> 4, n4 = idx & 15;
        cpasync16(sbase + (uint32_t)(KR_OFF + c * 64 + 4 * n4) * 4u,
                  kb + c * NPIX + 4 * n4);
    }
    asm volatile("cp.async.commit_group;" ::: "memory");
    #pragma unroll
    for (int i = 0; i < 16; ++i) {
        int idx = i * THREADS + tid;
        int c = idx >> 4, n4 = idx & 15;
        cpasync16(sbase + (uint32_t)(VS_OFF + c * P + 4 * n4) * 4u,
                  vb + c * NPIX + 4 * n4);
    }
    asm volatile("cp.async.commit_group;" ::: "memory");

    // Stage Q hi/lo bf16x2 into K region (pitch KP), then lift to registers
    #pragma unroll
    for (int it = 0; it < 2; ++it) {
        int slot = it * THREADS + tid;
        int cp = slot >> 4, m4 = slot & 15;
        const float* q0p = qb + (2 * cp) * NPIX + 4 * m4;
        float4 qe = *(const float4*)(q0p);
        float4 qo = *(const float4*)(q0p + NPIX);
        float xe[4] = {qe.x, qe.y, qe.z, qe.w};
        float xo[4] = {qo.x, qo.y, qo.z, qo.w};
        uint32_t hv[4], lv[4];
        #pragma unroll
        for (int r = 0; r < 4; ++r) {
            uint32_t h = bf16x2p(xo[r], xe[r]);
            hv[r] = h;
            lv[r] = bf16x2p(xo[r] - bfHI(h), xe[r] - bfLO(h));
        }
        *(uint4*)(KhW + cp * KP + 4 * m4) = *(uint4*)hv;
        *(uint4*)(KlW + cp * KP + 4 * m4) = *(uint4*)lv;
    }
    if (tid < MQ) Dn[tid] = 0.f;
    __syncthreads();

    uint32_t qh_r[4][4], ql_r[4][4];
    #pragma unroll
    for (int cs = 0; cs < 4; ++cs) {
        const int cb = cs * 8;
        qh_r[cs][0] = KhW[(cb + tq) * KP + q0 + g];
        qh_r[cs][1] = KhW[(cb + tq) * KP + q0 + g + 8];
        qh_r[cs][2] = KhW[(cb + tq + 4) * KP + q0 + g];
        qh_r[cs][3] = KhW[(cb + tq + 4) * KP + q0 + g + 8];
        ql_r[cs][0] = KlW[(cb + tq) * KP + q0 + g];
        ql_r[cs][1] = KlW[(cb + tq) * KP + q0 + g + 8];
        ql_r[cs][2] = KlW[(cb + tq + 4) * KP + q0 + g];
        ql_r[cs][3] = KlW[(cb + tq + 4) * KP + q0 + g + 8];
    }

    float d[2][8][4];
    #pragma unroll
    for (int i = 0; i < 2; ++i)
        #pragma unroll
        for (int j = 0; j < 8; ++j)
            #pragma unroll
            for (int r = 0; r < 4; ++r) d[i][j][r] = 0.f;

    // ---------- main loop ----------
    #pragma unroll 1
    for (int t = 0; t < NTILES; ++t) {
        const bool prod = (t + 1 < NTILES);

        // P0: Kraw(t) arrived (leave V(t) pending); barrier also retires
        //     readout(t-1) and Q extraction.
        asm volatile("cp.async.wait_group 1;" ::: "memory");
        __syncthreads();

        // P1: convert Kraw(t) -> Kh/Kl (LDS from smem, no LDG latency)
        #pragma unroll
        for (int it = 0; it < 2; ++it) {
            int slot = it * THREADS + tid;
            int cp = slot >> 4, n4 = slot & 15;
            float4 ke = *(const float4*)(KrF + (2 * cp) * 64 + 4 * n4);
            float4 ko = *(const float4*)(KrF + (2 * cp + 1) * 64 + 4 * n4);
            float xe[4] = {ke.x, ke.y, ke.z, ke.w};
            float xo[4] = {ko.x, ko.y, ko.z, ko.w};
            uint32_t hv[4], lv[4];
            #pragma unroll
            for (int r = 0; r < 4; ++r) {
                uint32_t h = bf16x2p(xo[r], xe[r]);
                hv[r] = h;
                lv[r] = bf16x2p(xo[r] - bfHI(h), xe[r] - bfLO(h));
            }
            *(uint4*)(KhW + cp * KP + 4 * n4) = *(uint4*)hv;
            *(uint4*)(KlW + cp * KP + 4 * n4) = *(uint4*)lv;
        }
        __syncthreads();   // K(t) ready; Kraw(t) consumed

        // P2: prefetch Kraw(t+1) (flies during logit+exp+readout)
        if (prod) {
            const int n0n = (t + 1) * NT;
            #pragma unroll
            for (int i = 0; i < 4; ++i) {
                int idx = i * THREADS + tid;
                int c = idx >> 4, n4 = idx & 15;
                cpasync16(sbase + (uint32_t)(KR_OFF + c * 64 + 4 * n4) * 4u,
                          kb + c * NPIX + n0n + 4 * n4);
            }
            asm volatile("cp.async.commit_group;" ::: "memory");
        }

        // ||k||^2 (warps 0-1); banks (8cp+k) conflict-free
        if (tid < NT) {
            float s = 0.f;
            #pragma unroll
            for (int cp = 0; cp < 32; ++cp) {
                uint32_t wh = KhW[cp * KP + tid], wl = KlW[cp * KP + tid];
                float ke = bfLO(wh) + bfLO(wl);
                float ko = bfHI(wh) + bfHI(wl);
                s = fmaf(ke, ke, fmaf(ko, ko, s));
            }
            S2[tid] = s;
        }

        // Logit MMA: warp = 16q x 32k, 3x bf16-split; Q from registers
        float dl[4][4];
        #pragma unroll
        for (int j = 0; j < 4; ++j)
            #pragma unroll
            for (int r = 0; r < 4; ++r) dl[j][r] = 0.f;
        #pragma unroll
        for (int cs = 0; cs < 4; ++cs) {
            const int cb = cs * 8;
            #pragma unroll
            for (int j = 0; j < 4; ++j) {
                const int kk0 = kh0 + 8 * j;
                uint32_t bh[2], bl2[2];
                bh[0]  = KhW[(cb + tq) * KP + kk0 + g];
                bh[1]  = KhW[(cb + tq + 4) * KP + kk0 + g];
                bl2[0] = KlW[(cb + tq) * KP + kk0 + g];
                bl2[1] = KlW[(cb + tq + 4) * KP + kk0 + g];
                mma_bf16(dl[j], qh_r[cs], bh);
                mma_bf16(dl[j], qh_r[cs], bl2);
                mma_bf16(dl[j], ql_r[cs], bh);
            }
        }
        __syncthreads();   // all K reads + S2 done -> Et may overlay K region

        // P3: exp -> Et[q][k] (tf32 bits) + denominator
        {
            const float C1 = 0.125f * 1.4426950408889634f;   // log2(e)/8
            float pA = 0.f, pB = 0.f;
            #pragma unroll
            for (int j = 0; j < 4; ++j) {
                const int kk = kh0 + 8 * j + 2 * tq;
                float2 s2v = *(const float2*)(S2 + kk);
                float sbx = s2v.x * C1, sby = s2v.y * C1;
                float e0 = exp2f(fmaf(dl[j][0], 2.f * C1, -sbx));
                float e1 = exp2f(fmaf(dl[j][1], 2.f * C1, -sby));
                float e2 = exp2f(fmaf(dl[j][2], 2.f * C1, -sbx));
                float e3 = exp2f(fmaf(dl[j][3], 2.f * C1, -sby));
                *(float2*)(Et + (q0 + g) * P + kk)     = make_float2(tf32r(e0), tf32r(e1));
                *(float2*)(Et + (q0 + g + 8) * P + kk) = make_float2(tf32r(e2), tf32r(e3));
                pA += e0 + e1;
                pB += e2 + e3;
            }
            pA += __shfl_xor_sync(0xffffffffu, pA, 1);
            pA += __shfl_xor_sync(0xffffffffu, pA, 2);
            pB += __shfl_xor_sync(0xffffffffu, pB, 1);
            pB += __shfl_xor_sync(0xffffffffu, pB, 2);
            if (tq == 0) {
                atomicAdd(&Dn[q0 + g], pA);
                atomicAdd(&Dn[q0 + g + 8], pB);
            }
        }

        // P4: ensure V(t) landed (keep Kraw(t+1) pending when it exists)
        if (prod) {
            asm volatile("cp.async.wait_group 1;" ::: "memory");
        } else {
            asm volatile("cp.async.wait_group 0;" ::: "memory");
        }
        __syncthreads();   // Et + V visible to all

        // P5: readout(t): D[32ch x 64q] += V * Et^T (tf32; V raw fp32, RZ trunc)
        {
            const uint32_t* Eu = (const uint32_t*)Et;
            #pragma unroll
            for (int s = 0; s < 8; ++s) {
                const int k0 = s * 8;
                uint32_t a[2][4];
                #pragma unroll
                for (int i = 0; i < 2; ++i) {
                    int row = ch0 + 16 * i + g;
                    a[i][0] = VsW[row * P + k0 + tq];
                    a[i][1] = VsW[(row + 8) * P + k0 + tq];
                    a[i][2] = VsW[row * P + k0 + tq + 4];
                    a[i][3] = VsW[(row + 8) * P + k0 + tq + 4];
                }
                uint32_t bfr[8][2];
                #pragma unroll
                for (int j = 0; j < 8; ++j) {
                    int q = j * 8 + g;
                    bfr[j][0] = Eu[q * P + k0 + tq];
                    bfr[j][1] = Eu[q * P + k0 + tq + 4];
                }
                #pragma unroll
                for (int i = 0; i < 2; ++i)
                    #pragma unroll
                    for (int j = 0; j < 8; ++j)
                        mma_tf32(d[i][j], a[i], bfr[j]);
            }
        }
        __syncthreads();   // V(t)/Et(t) free

        // P6: launch V(t+1)
        if (prod) {
            const int n0n = (t + 1) * NT;
            #pragma unroll
            for (int i = 0; i < 16; ++i) {
                int idx = i * THREADS + tid;
                int c = idx >> 4, n4 = idx & 15;
                cpasync16(sbase + (uint32_t)(VS_OFF + c * P + 4 * n4) * 4u,
                          vb + c * NPIX + n0n + 4 * n4);
            }
            asm volatile("cp.async.commit_group;" ::: "memory");
        }
    }

    __syncthreads();
    if (tid < MQ) Dn[tid] = 1.0f / Dn[tid];
    __syncthreads();

    // Epilogue
    #pragma unroll
    for (int i = 0; i < 2; ++i) {
        int ch = zc + ch0 + 16 * i + g;
        float* op0 = out + ((size_t)b * CVc + ch) * NPIX + m0;
        float* op1 = out + ((size_t)b * CVc + ch + 8) * NPIX + m0;
        #pragma unroll
        for (int j = 0; j < 8; ++j) {
            int q = j * 8 + 2 * tq;
            float2 dn2 = *(const float2*)(Dn + q);
            *(float2*)(op0 + q) = make_float2(d[i][j][0] * dn2.x, d[i][j][1] * dn2.y);
            *(float2*)(op1 + q) = make_float2(d[i][j][2] * dn2.x, d[i][j][3] * dn2.y);
        }
    }
}

extern "C" void kernel_launch(void* const* d_in, const int* in_sizes, int n_in,
                              void* d_out, int out_size)
{
    const float* mk = (const float*)d_in[0];
    const float* qk = (const float*)d_in[1];
    const float* mv = (const float*)d_in[2];
    const float* qv = (const float*)d_in[3];
    float* out = (float*)d_out;

    size_t smem = (size_t)SMEM_W * sizeof(float);   // 104960 B
    cudaFuncSetAttribute(mr_attn_kernel, cudaFuncAttributeMaxDynamicSharedMemorySize, (int)smem);

    dim3 grid(NPIX / MQ, Bsz, 2);   // 49 x 16 x 2
    mr_attn_kernel<<<grid, THREADS, smem>>>(mk, qk, mv, out);

    size_t memElems = (size_t)Bsz * CVc * NPIX;
    if ((size_t)out_size >= 2 * memElems) {
        cudaMemcpyAsync(out + memElems, qv, memElems * sizeof(float),
                        cudaMemcpyDeviceToDevice);
    }
}